// round 15
// baseline (speedup 1.0000x reference)
#include <cuda_runtime.h>
#include <cuda_bf16.h>
#include <cuda_fp16.h>
#include <cstdint>

#define H 64
#define MAXN 100000
#define MAXE 1600000
#define MAXL 8

typedef unsigned long long u64;

// ---------------- device scratch (static: no dynamic allocation allowed) ----
__device__ float         g_h[(size_t)MAXN * H];
__device__ float         g_A[(size_t)MAXN * H];
__device__ unsigned int  g_aggr[(size_t)MAXN * H];
__device__ int           g_cnt[MAXN];
__device__ int           g_cursor[MAXN];
__device__ int           g_perm[MAXE];
__device__ __half        g_Bh[MAXL * 64 * 72];        // edge W2^T fp16 [n][72]
__device__ __half        g_NBh[MAXL * 4 * 64 * 72];   // node weights fp16 [l][g][n][72]
__device__ __half        g_ND[MAXL * 2 * 64 * 72];    // dual B: [uw2^T | (uw2@mw1')^T]
__device__ float         g_bdual[MAXL * 128];         // dual biases [ub2 | b']
__device__ float         g_fcw2[65];                  // folded fc: uw2@fcw, bias

// order-preserving float<->uint encoding for atomic min
__device__ __forceinline__ unsigned fenc(float f) {
    unsigned u = __float_as_uint(f);
    return (u & 0x80000000u) ? ~u : (u | 0x80000000u);
}
__device__ __forceinline__ float fdec(unsigned u) {
    return (u & 0x80000000u) ? __uint_as_float(u & 0x7FFFFFFFu)
                             : __uint_as_float(~u);
}

// -------- warp-mma plumbing (plain sm_80+ PTX) -----------------------------
__device__ __forceinline__ uint32_t smem_u32(const void* p) {
    uint32_t a;
    asm("{ .reg .u64 t; cvta.to.shared.u64 t, %1; cvt.u32.u64 %0, t; }"
        : "=r"(a) : "l"(p));
    return a;
}
__device__ __forceinline__ void ldsm4(uint32_t (&r)[4], uint32_t addr) {
    asm volatile("ldmatrix.sync.aligned.m8n8.x4.shared.b16 {%0,%1,%2,%3}, [%4];"
                 : "=r"(r[0]), "=r"(r[1]), "=r"(r[2]), "=r"(r[3]) : "r"(addr));
}
__device__ __forceinline__ void mma16816h(float (&d)[4], const uint32_t (&a)[4],
                                          uint32_t b0, uint32_t b1) {
    asm volatile(
        "mma.sync.aligned.m16n8k16.row.col.f32.f16.f16.f32 "
        "{%0,%1,%2,%3}, {%4,%5,%6,%7}, {%8,%9}, {%0,%1,%2,%3};"
        : "+f"(d[0]), "+f"(d[1]), "+f"(d[2]), "+f"(d[3])
        : "r"(a[0]), "r"(a[1]), "r"(a[2]), "r"(a[3]), "r"(b0), "r"(b1));
}
// pack f16(even)|f16(odd)<<16
__device__ __forceinline__ uint32_t cvt2h(float odd, float even) {
    uint32_t d;
    asm("cvt.rn.f16x2.f32 %0, %1, %2;" : "=r"(d) : "f"(odd), "f"(even));
    return d;
}

// ---------------- trivial elementwise kernels ------------------------------
__global__ void embed_kernel(const float* __restrict__ x,
                             const float* __restrict__ w,
                             const float* __restrict__ b,
                             float* __restrict__ h, int* __restrict__ cnt,
                             int n) {
    int i = blockIdx.x * blockDim.x + threadIdx.x;
    if (i < n) cnt[i] = 0;
    if (i < n * H) {
        int node = i >> 6, j = i & 63;
        h[i] = fmaf(x[node], w[j], b[j]);
    }
}

__global__ void count_kernel(const int* __restrict__ dst, int* cnt, int e) {
    int i = blockIdx.x * blockDim.x + threadIdx.x;
    if (i < e) atomicAdd(&cnt[dst[i]], 1);
}

// prefix scan of cnt + all fp16 weight prep (edge B, node B, dual B, fc fold)
__global__ void scan_prep_kernel(const int* __restrict__ cnt,
                                 int* __restrict__ cursor, int n,
                                 const float* __restrict__ mw2,
                                 const float* __restrict__ mw1,
                                 const float* __restrict__ uw1,
                                 const float* __restrict__ uw2,
                                 const float* __restrict__ ub2,
                                 const float* __restrict__ mb1,
                                 const float* __restrict__ fcw,
                                 const float* __restrict__ fcb, int L) {
    int tid = threadIdx.x;
    int total = L * H * H;
    for (int i = tid; i < total; i += 1024) {
        int l = i >> 12, rem = i & 4095;
        int nn = rem >> 6, k = rem & 63;
        float w = mw2[(size_t)l * 4096 + k * 64 + nn];
        g_Bh[(size_t)l * (64 * 72) + nn * 72 + k] = __float2half_rn(w);
    }
    int totN = L * 4 * 4096;
    for (int i = tid; i < totN; i += 1024) {
        int l = i >> 14;
        int g = (i >> 12) & 3;
        int rem = i & 4095;
        int nn = rem >> 6, k = rem & 63;
        float w;
        if (g == 0)      w = mw1[(size_t)l * 65 * 64 + k * 64 + nn];
        else if (g <= 2) w = uw1[(size_t)l * 128 * 64 + ((g - 1) * 64 + k) * 64 + nn];
        else             w = uw2[(size_t)l * 64 * 64 + k * 64 + nn];
        g_NBh[(size_t)(l * 4 + g) * 4608 + nn * 72 + k] = __float2half_rn(w);
    }
    // dual-output B chunks (layers 0..L-2): [uw2^T | (uw2 @ mw1_{l+1})^T]
    int totD = (L - 1) * 2 * 4096;
    for (int i = tid; i < totD; i += 1024) {
        int l = i >> 13;
        int g = (i >> 12) & 1;
        int rem = i & 4095;
        int nn = rem >> 6, k = rem & 63;
        float w;
        if (g == 0) {
            w = uw2[(size_t)l * 4096 + k * 64 + nn];
        } else {
            float s = 0.f;
            const float* u = uw2 + (size_t)l * 4096 + k * 64;
            const float* m = mw1 + (size_t)(l + 1) * 65 * 64;
            for (int j = 0; j < 64; j++) s += u[j] * m[j * 64 + nn];
            w = s;
        }
        g_ND[(size_t)(l * 2 + g) * 4608 + nn * 72 + k] = __float2half_rn(w);
    }
    // combined biases: [ub2 | ub2 @ mw1_{l+1} + mb1_{l+1}]
    for (int i = tid; i < (L - 1) * 128; i += 1024) {
        int l = i >> 7, c = i & 127;
        if (c < 64) {
            g_bdual[l * 128 + c] = ub2[(size_t)l * 64 + c];
        } else {
            int nn = c - 64;
            float s = mb1[(size_t)(l + 1) * 64 + nn];
            const float* m = mw1 + (size_t)(l + 1) * 65 * 64;
            for (int j = 0; j < 64; j++)
                s += ub2[(size_t)l * 64 + j] * m[j * 64 + nn];
            g_bdual[l * 128 + c] = s;
        }
    }
    // folded fc: out = tmp @ (uw2@fcw) + (ub2.fcw + fcb)
    for (int i = tid; i < 65; i += 1024) {
        if (i < 64) {
            float s = 0.f;
            const float* u = uw2 + (size_t)(L - 1) * 4096 + i * 64;
            for (int j = 0; j < 64; j++) s += u[j] * fcw[j];
            g_fcw2[i] = s;
        } else {
            float s = fcb[0];
            for (int j = 0; j < 64; j++)
                s += ub2[(size_t)(L - 1) * 64 + j] * fcw[j];
            g_fcw2[64] = s;
        }
    }
    __shared__ int s[1024];
    int chunk = (n + 1023) >> 10;
    int lo = tid * chunk;
    int hi = min(lo + chunk, n);
    int sum = 0;
    for (int i = lo; i < hi; i++) sum += cnt[i];
    s[tid] = sum;
    __syncthreads();
    for (int off = 1; off < 1024; off <<= 1) {
        int v = (tid >= off) ? s[tid - off] : 0;
        __syncthreads();
        s[tid] += v;
        __syncthreads();
    }
    int run = s[tid] - sum;
    for (int i = lo; i < hi; i++) { cursor[i] = run; run += cnt[i]; }
}

// scatter (build perm) + init aggr to encoded +inf
__global__ void scatter_kernel(const int* __restrict__ dst, int* cursor,
                               int* perm, unsigned* __restrict__ aggr,
                               int e, int nH4) {
    int i = blockIdx.x * blockDim.x + threadIdx.x;
    if (i < e) {
        int p = atomicAdd(&cursor[dst[i]], 1);
        perm[p] = i;
    }
    uint4 f = make_uint4(~0u, ~0u, ~0u, ~0u);
    for (int j = i; j < nH4; j += gridDim.x * blockDim.x)
        ((uint4*)aggr)[j] = f;
}

__global__ void fc_kernel(const float* __restrict__ h,
                          const float* __restrict__ fcw,
                          const float* __restrict__ fcb,
                          float* __restrict__ out, int n) {
    int i = blockIdx.x * blockDim.x + threadIdx.x;
    if (i >= n) return;
    const float4* h4 = (const float4*)(h + (size_t)i * H);
    const float4* w4 = (const float4*)fcw;
    float s = 0.f;
#pragma unroll
    for (int q = 0; q < 16; q++) {
        float4 a = h4[q], w = w4[q];
        s += a.x * w.x + a.y * w.y + a.z * w.z + a.w * w.w;
    }
    out[i] = s + fcb[0];
}

// ---------------- node GEMM via HMMA, single-term fp16 ---------------------
#define NM_B_OFF 18432

template <int NC, bool RELU, bool DECODE>
__global__ void __launch_bounds__(128, 4)
node_mma(const float* __restrict__ X1, const unsigned* __restrict__ X2,
         const __half* __restrict__ NBh_g,
         const float* __restrict__ bias, const float* __restrict__ b2g,
         unsigned* __restrict__ aggrw, float* __restrict__ C, int Nn) {
    extern __shared__ char smc[];
    uint32_t sb = smem_u32(smc);
    int tid = threadIdx.x;
    int lane = tid & 31;
    int wid = tid >> 5;
    const int BIAS_OFF = NM_B_OFF + NC * 9216;

    {
        const uint4* sh = (const uint4*)NBh_g;
        for (int i = tid; i < NC * 576; i += 128)
            ((uint4*)(smc + NM_B_OFF))[i] = sh[i];
        if (tid < 64) ((float*)(smc + BIAS_OFF))[tid] = bias[tid];
        if (DECODE && tid >= 64 && tid < 128)
            ((float*)(smc + BIAS_OFF))[tid] = b2g[tid - 64];
    }
    __syncthreads();

    int n0 = blockIdx.x * 128;
    int m0base = n0 + wid * 32;
    char* Tw = smc + wid * 4608;
    uint32_t sbT = sb + wid * 4608;

    uint32_t aRow = (lane & 7) + 8u * ((lane >> 3) & 1);
    uint32_t aKoff = 16u * (lane >> 4);
    uint32_t bBase = 144u * (8u * ((lane >> 4) & 1) + (lane & 7)) +
                     16u * ((lane >> 3) & 1);
    int gc = lane & 15, gh = lane >> 4;

    float acc[2][8][4];
#pragma unroll
    for (int mt = 0; mt < 2; mt++)
#pragma unroll
        for (int nt = 0; nt < 8; nt++)
#pragma unroll
            for (int c = 0; c < 4; c++) acc[mt][nt][c] = 0.f;

#pragma unroll
    for (int c = 0; c < NC; c++) {
#pragma unroll 4
        for (int rp = 0; rp < 16; rp++) {
            int r = rp * 2 + gh;
            int rowu = m0base + r;
            int row = min(rowu, Nn - 1);
            float v0, v1, v2, v3;
            if (DECODE && c == 1) {
                uint4 u = ((const uint4*)(X2 + (size_t)row * H))[gc];
                float4 b2v = ((const float4*)(smc + BIAS_OFF + 256))[gc];
                v0 = (u.x >= 0xFF800000u) ? 0.f : (fdec(u.x) + b2v.x);
                v1 = (u.y >= 0xFF800000u) ? 0.f : (fdec(u.y) + b2v.y);
                v2 = (u.z >= 0xFF800000u) ? 0.f : (fdec(u.z) + b2v.z);
                v3 = (u.w >= 0xFF800000u) ? 0.f : (fdec(u.w) + b2v.w);
                if (rowu < Nn)
                    ((uint4*)(aggrw + (size_t)row * H))[gc] =
                        make_uint4(~0u, ~0u, ~0u, ~0u);
            } else {
                float4 a = ((const float4*)(X1 + (size_t)row * H))[gc];
                v0 = a.x; v1 = a.y; v2 = a.z; v3 = a.w;
            }
            *(uint2*)(Tw + r * 144 + gc * 8) =
                make_uint2(cvt2h(v1, v0), cvt2h(v3, v2));
        }
        __syncwarp();

        uint32_t Bc = sb + NM_B_OFF + c * 9216;
#pragma unroll
        for (int ks = 0; ks < 4; ks++) {
            uint32_t ah0[4], ah1[4];
            ldsm4(ah0, sbT + 144u * aRow + 32u * ks + aKoff);
            ldsm4(ah1, sbT + 144u * (16 + aRow) + 32u * ks + aKoff);
#pragma unroll
            for (int ntp = 0; ntp < 4; ntp++) {
                uint32_t bh[4];
                ldsm4(bh, Bc + bBase + 2304u * ntp + 32u * ks);
                mma16816h(acc[0][2 * ntp], ah0, bh[0], bh[1]);
                mma16816h(acc[1][2 * ntp], ah1, bh[0], bh[1]);
                mma16816h(acc[0][2 * ntp + 1], ah0, bh[2], bh[3]);
                mma16816h(acc[1][2 * ntp + 1], ah1, bh[2], bh[3]);
            }
        }
        __syncwarp();
    }

    const float* bs = (const float*)(smc + BIAS_OFF);
#pragma unroll
    for (int mt = 0; mt < 2; mt++) {
        int row = m0base + mt * 16 + (lane >> 2);
        int colb = (lane & 3) * 2;
#pragma unroll
        for (int nt = 0; nt < 8; nt++) {
            int cc = nt * 8 + colb;
            float b0 = bs[cc], b1 = bs[cc + 1];
            float2 v0 = make_float2(acc[mt][nt][0] + b0, acc[mt][nt][1] + b1);
            float2 v1 = make_float2(acc[mt][nt][2] + b0, acc[mt][nt][3] + b1);
            if (RELU) {
                v0.x = fmaxf(v0.x, 0.f); v0.y = fmaxf(v0.y, 0.f);
                v1.x = fmaxf(v1.x, 0.f); v1.y = fmaxf(v1.y, 0.f);
            }
            if (row < Nn)
                *(float2*)(C + (size_t)row * H + cc) = v0;
            if (row + 8 < Nn)
                *(float2*)(C + (size_t)(row + 8) * H + cc) = v1;
        }
    }
}

// ---------------- dual-output node GEMM ------------------------------------
// From one T (tmp): h' = tmp @ uw2 + ub2 -> hout; A' = tmp @ W' + b' -> Aout
// (W' = uw2 @ mw1_{l+1} pre-multiplied fp32->fp16). In-place safe: each warp
// reads its own 32 tmp rows into smem before the epilogue writes them.
#define ND_B_OFF 18432
#define ND_BIAS  36864
#define SMEM_ND  37376

__global__ void __launch_bounds__(128, 4)
node_dual(const float* __restrict__ X1, const __half* __restrict__ Bg,
          const float* __restrict__ bg, float* __restrict__ hout,
          float* __restrict__ Aout, int Nn) {
    extern __shared__ char smc[];
    uint32_t sb = smem_u32(smc);
    int tid = threadIdx.x, lane = tid & 31, wid = tid >> 5;

    for (int i = tid; i < 1152; i += 128)
        ((uint4*)(smc + ND_B_OFF))[i] = ((const uint4*)Bg)[i];
    if (tid < 128) ((float*)(smc + ND_BIAS))[tid] = bg[tid];
    __syncthreads();

    int m0base = blockIdx.x * 128 + wid * 32;
    char* Tw = smc + wid * 4608;
    uint32_t sbT = sb + wid * 4608;

    uint32_t aRow = (lane & 7) + 8u * ((lane >> 3) & 1);
    uint32_t aKoff = 16u * (lane >> 4);
    uint32_t bBase = 144u * (8u * ((lane >> 4) & 1) + (lane & 7)) +
                     16u * ((lane >> 3) & 1);
    int gc = lane & 15, gh = lane >> 4;

    // T-fill (coalesced, fp16)
#pragma unroll 4
    for (int rp = 0; rp < 16; rp++) {
        int r = rp * 2 + gh;
        int row = min(m0base + r, Nn - 1);
        float4 a = ((const float4*)(X1 + (size_t)row * H))[gc];
        *(uint2*)(Tw + r * 144 + gc * 8) =
            make_uint2(cvt2h(a.y, a.x), cvt2h(a.w, a.z));
    }
    __syncwarp();

    const float* bs = (const float*)(smc + ND_BIAS);
#pragma unroll
    for (int nh = 0; nh < 2; nh++) {
        float acc[2][8][4];
#pragma unroll
        for (int mt = 0; mt < 2; mt++)
#pragma unroll
            for (int nt = 0; nt < 8; nt++)
#pragma unroll
                for (int c = 0; c < 4; c++) acc[mt][nt][c] = 0.f;

        uint32_t Bc = sb + ND_B_OFF + nh * 9216;
#pragma unroll
        for (int ks = 0; ks < 4; ks++) {
            uint32_t ah0[4], ah1[4];
            ldsm4(ah0, sbT + 144u * aRow + 32u * ks + aKoff);
            ldsm4(ah1, sbT + 144u * (16 + aRow) + 32u * ks + aKoff);
#pragma unroll
            for (int ntp = 0; ntp < 4; ntp++) {
                uint32_t bh[4];
                ldsm4(bh, Bc + bBase + 2304u * ntp + 32u * ks);
                mma16816h(acc[0][2 * ntp], ah0, bh[0], bh[1]);
                mma16816h(acc[1][2 * ntp], ah1, bh[0], bh[1]);
                mma16816h(acc[0][2 * ntp + 1], ah0, bh[2], bh[3]);
                mma16816h(acc[1][2 * ntp + 1], ah1, bh[2], bh[3]);
            }
        }

        float* C = nh ? Aout : hout;
        const float* bb = bs + nh * 64;
#pragma unroll
        for (int mt = 0; mt < 2; mt++) {
            int row = m0base + mt * 16 + (lane >> 2);
            int colb = (lane & 3) * 2;
#pragma unroll
            for (int nt = 0; nt < 8; nt++) {
                int cc = nt * 8 + colb;
                float b0 = bb[cc], b1 = bb[cc + 1];
                float2 v0 = make_float2(acc[mt][nt][0] + b0,
                                        acc[mt][nt][1] + b1);
                float2 v1 = make_float2(acc[mt][nt][2] + b0,
                                        acc[mt][nt][3] + b1);
                if (row < Nn)
                    *(float2*)(C + (size_t)row * H + cc) = v0;
                if (row + 8 < Nn)
                    *(float2*)(C + (size_t)(row + 8) * H + cc) = v1;
            }
        }
    }
}

// ---------------- HMMA edge kernel (R13: coalesced + metadata prefetch) ----
#define TW_STRIDE 8192
#define BH_OFF   32768
#define WES_OFF  41984
#define DST_OFF  42240
#define SMEM_EDGE 42752

__global__ void __launch_bounds__(128, 4)
edge_mma_kernel(const float* __restrict__ Ag, const int* __restrict__ src,
                const int* __restrict__ dstp, const float* __restrict__ ea,
                const int* __restrict__ perm, const float* __restrict__ weg,
                const __half* __restrict__ Bh_g,
                unsigned* __restrict__ aggr, int E, int nt32) {
    extern __shared__ char smc[];
    uint32_t sb = smem_u32(smc);
    int tid = threadIdx.x;
    int lane = tid & 31;
    int wid = tid >> 5;

    {
        const uint4* s4 = (const uint4*)Bh_g;
        uint4* d4 = (uint4*)(smc + BH_OFF);
        for (int i = tid; i < 576; i += 128) d4[i] = s4[i];
        if (tid < 64) ((float*)(smc + WES_OFF))[tid] = weg[tid];
    }
    __syncthreads();

    const float* wes = (const float*)(smc + WES_OFF);
    char* Tw = smc + wid * TW_STRIDE;
    uint32_t sbT = sb + wid * TW_STRIDE;
    float* Ds = (float*)Tw;
    int* dstw = (int*)(smc + DST_OFF + wid * 128);

    uint32_t aRow = (lane & 7) + 8u * ((lane >> 3) & 1);
    uint32_t aKoff = 16u * (lane >> 4);
    uint32_t bBase = 144u * (8u * ((lane >> 4) & 1) + (lane & 7)) +
                     16u * ((lane >> 3) & 1);

    int gc = lane & 15;
    int ghalf = lane >> 4;
    float4 wch = ((const float4*)wes)[gc];

    int step = gridDim.x * 4;
    int t = blockIdx.x * 4 + wid;

    // preload first tile's metadata (perm -> src/ea/dst chain)
    int s = 0, dv = -1;
    float ev = 0.f;
    if (t < nt32) {
        int slot = t * 32 + lane;
        int eidx = perm[min(slot, E - 1)];
        s = src[eidx];
        ev = ea[eidx];
        dv = (slot < E) ? dstp[eidx] : -1;
    }

    for (; t < nt32; t += step) {
        dstw[lane] = dv;
        // ---- coalesced gather + relu + fp16 -> T rows (uses s, ev) ----
#pragma unroll
        for (int rp = 0; rp < 16; rp++) {
            int r = rp * 2 + ghalf;
            int srow = __shfl_sync(0xFFFFFFFFu, s, r);
            float evr = __shfl_sync(0xFFFFFFFFu, ev, r);
            float4 a = ((const float4*)(Ag + (size_t)srow * H))[gc];
            float v0 = fmaxf(fmaf(evr, wch.x, a.x), 0.f);
            float v1 = fmaxf(fmaf(evr, wch.y, a.y), 0.f);
            float v2 = fmaxf(fmaf(evr, wch.z, a.z), 0.f);
            float v3 = fmaxf(fmaf(evr, wch.w, a.w), 0.f);
            uint2 hp;
            hp.x = cvt2h(v1, v0);
            hp.y = cvt2h(v3, v2);
            *(uint2*)(Tw + r * 144 + gc * 8) = hp;
        }
        __syncwarp();

        // ---- prefetch next tile's metadata (overlaps MMA + epilogue) ----
        {
            int tn = t + step;
            if (tn < nt32) {
                int slotn = tn * 32 + lane;
                int eidxn = perm[min(slotn, E - 1)];
                s = src[eidxn];
                ev = ea[eidxn];
                dv = (slotn < E) ? dstp[eidxn] : -1;
            }
        }

        // ---- warp MMA: 2 m16-tiles (rows 0/16), 4 k-steps ----
        float acc[2][8][4];
#pragma unroll
        for (int mt = 0; mt < 2; mt++)
#pragma unroll
            for (int nt = 0; nt < 8; nt++)
#pragma unroll
                for (int c = 0; c < 4; c++) acc[mt][nt][c] = 0.f;

#pragma unroll
        for (int ks = 0; ks < 4; ks++) {
            uint32_t ah0[4], ah1[4];
            ldsm4(ah0, sbT + 144u * aRow + 32u * ks + aKoff);
            ldsm4(ah1, sbT + 144u * (16 + aRow) + 32u * ks + aKoff);
#pragma unroll
            for (int ntp = 0; ntp < 4; ntp++) {
                uint32_t b4[4];
                ldsm4(b4, sb + BH_OFF + bBase + 2304u * ntp + 32u * ks);
                mma16816h(acc[0][2 * ntp], ah0, b4[0], b4[1]);
                mma16816h(acc[1][2 * ntp], ah1, b4[0], b4[1]);
                mma16816h(acc[0][2 * ntp + 1], ah0, b4[2], b4[3]);
                mma16816h(acc[1][2 * ntp + 1], ah1, b4[2], b4[3]);
            }
        }
        __syncwarp();   // T reads done before Ds overlay writes

        // ---- stage D to swizzled SMEM: float4 slot = e*16 + (c4^(e&15)) ----
#pragma unroll
        for (int mt = 0; mt < 2; mt++) {
            int eb = mt * 16 + (lane >> 2);
            int h2i = lane & 1;
            int c4b = (lane & 3) >> 1;
#pragma unroll
            for (int nt = 0; nt < 8; nt++) {
                int c4 = nt * 2 + c4b;
                float2 v0 = make_float2(acc[mt][nt][0], acc[mt][nt][1]);
                float2 v1 = make_float2(acc[mt][nt][2], acc[mt][nt][3]);
                int e0 = eb, e1 = eb + 8;
                ((float2*)(Ds + (e0 * 16 + (c4 ^ (e0 & 15))) * 4))[h2i] = v0;
                ((float2*)(Ds + (e1 * 16 + (c4 ^ (e1 & 15))) * 4))[h2i] = v1;
            }
        }
        __syncwarp();

        // ---- epilogue: segmented min over 8 sorted edges, atomicMin ----
        {
            const float4* Ds4 = (const float4*)Ds;
            int ty = lane >> 3, tx = lane & 7;
            int cur = -2;
            float4 mA, mB;
#pragma unroll
            for (int r = 0; r < 8; r++) {
                int e = ty * 8 + r;
                int d = dstw[e];
                float4 a = Ds4[e * 16 + (tx ^ (e & 15))];
                float4 b = Ds4[e * 16 + ((8 + tx) ^ (e & 15))];
                if (r == 0 || d != cur) {
                    if (r > 0 && cur >= 0) {
                        unsigned* p0 = aggr + (size_t)cur * H + tx * 4;
                        atomicMin(p0 + 0, fenc(mA.x));
                        atomicMin(p0 + 1, fenc(mA.y));
                        atomicMin(p0 + 2, fenc(mA.z));
                        atomicMin(p0 + 3, fenc(mA.w));
                        unsigned* p1 = p0 + 32;
                        atomicMin(p1 + 0, fenc(mB.x));
                        atomicMin(p1 + 1, fenc(mB.y));
                        atomicMin(p1 + 2, fenc(mB.z));
                        atomicMin(p1 + 3, fenc(mB.w));
                    }
                    cur = d;
                    mA = a; mB = b;
                } else {
                    mA.x = fminf(mA.x, a.x); mA.y = fminf(mA.y, a.y);
                    mA.z = fminf(mA.z, a.z); mA.w = fminf(mA.w, a.w);
                    mB.x = fminf(mB.x, b.x); mB.y = fminf(mB.y, b.y);
                    mB.z = fminf(mB.z, b.z); mB.w = fminf(mB.w, b.w);
                }
            }
            if (cur >= 0) {
                unsigned* p0 = aggr + (size_t)cur * H + tx * 4;
                atomicMin(p0 + 0, fenc(mA.x));
                atomicMin(p0 + 1, fenc(mA.y));
                atomicMin(p0 + 2, fenc(mA.z));
                atomicMin(p0 + 3, fenc(mA.w));
                unsigned* p1 = p0 + 32;
                atomicMin(p1 + 0, fenc(mB.x));
                atomicMin(p1 + 1, fenc(mB.y));
                atomicMin(p1 + 2, fenc(mB.z));
                atomicMin(p1 + 3, fenc(mB.w));
            }
        }
        __syncwarp();   // Ds/dstw dead before next tile's gather writes
    }
}

// ---------------- host launch ----------------------------------------------
extern "C" void kernel_launch(void* const* d_in, const int* in_sizes, int n_in,
                              void* d_out, int out_size) {
    const float* x    = (const float*)d_in[0];
    const int*   ei   = (const int*)d_in[1];
    const float* ea   = (const float*)d_in[2];
    const float* embw = (const float*)d_in[3];
    const float* embb = (const float*)d_in[4];
    const float* mw1  = (const float*)d_in[5];
    const float* mb1  = (const float*)d_in[6];
    const float* mw2  = (const float*)d_in[7];
    const float* mb2  = (const float*)d_in[8];
    const float* uw1  = (const float*)d_in[9];
    const float* ub1  = (const float*)d_in[10];
    const float* uw2  = (const float*)d_in[11];
    const float* ub2  = (const float*)d_in[12];
    const float* fcw  = (const float*)d_in[13];
    const float* fcb  = (const float*)d_in[14];
    float* out = (float*)d_out;

    int N = in_sizes[0];
    int E = in_sizes[2];
    int L = in_sizes[6] / H;
    const int* src = ei;
    const int* dstp = ei + E;

    float* hbuf; float* Abuf; unsigned* aggr;
    int* cnt; int* cursor; int* perm;
    __half* Bh; __half* NBh; __half* ND; float* bdual; float* fcw2;
    cudaGetSymbolAddress((void**)&hbuf, g_h);
    cudaGetSymbolAddress((void**)&Abuf, g_A);
    cudaGetSymbolAddress((void**)&aggr, g_aggr);
    cudaGetSymbolAddress((void**)&cnt, g_cnt);
    cudaGetSymbolAddress((void**)&cursor, g_cursor);
    cudaGetSymbolAddress((void**)&perm, g_perm);
    cudaGetSymbolAddress((void**)&Bh, g_Bh);
    cudaGetSymbolAddress((void**)&NBh, g_NBh);
    cudaGetSymbolAddress((void**)&ND, g_ND);
    cudaGetSymbolAddress((void**)&bdual, g_bdual);
    cudaGetSymbolAddress((void**)&fcw2, g_fcw2);

    const int smN1 = NM_B_OFF + 1 * 9216 + 512;   // 28160
    const int smN2 = NM_B_OFF + 2 * 9216 + 512;   // 37376
    cudaFuncSetAttribute(edge_mma_kernel,
                         cudaFuncAttributeMaxDynamicSharedMemorySize, SMEM_EDGE);
    cudaFuncSetAttribute((node_mma<1, false, false>),
                         cudaFuncAttributeMaxDynamicSharedMemorySize, smN1);
    cudaFuncSetAttribute((node_mma<2, true, true>),
                         cudaFuncAttributeMaxDynamicSharedMemorySize, smN2);
    cudaFuncSetAttribute(node_dual,
                         cudaFuncAttributeMaxDynamicSharedMemorySize, SMEM_ND);

    int nt32 = (E + 31) / 32;
    int edgeGrid = 148 * 4;
    if (edgeGrid > (nt32 + 3) / 4) edgeGrid = (nt32 + 3) / 4;
    int nodeBlocks = (N + 127) / 128;

    // embedding (+ zero cnt)
    embed_kernel<<<(N * H + 255) / 256, 256>>>(x, embw, embb, hbuf, cnt, N);
    // counting sort by dst (+ all weight prep incl. folded duals, + poison)
    count_kernel<<<(E + 255) / 256, 256>>>(dstp, cnt, E);
    scan_prep_kernel<<<1, 1024>>>(cnt, cursor, N, mw2, mw1, uw1, uw2,
                                  ub2, mb1, fcw, fcb, L);
    scatter_kernel<<<(E + 255) / 256, 256>>>(dstp, cursor, perm, aggr, E,
                                             N * H / 4);

    // A_0 = h @ mw1(0)[:64] + mb1(0)
    node_mma<1, false, false><<<nodeBlocks, 128, smN1>>>(
        hbuf, nullptr, NBh, mb1, nullptr, nullptr, Abuf, N);

    for (int l = 0; l < L; l++) {
        const float* w1 = mw1 + (size_t)l * (H + 1) * H;   // [65,64]
        // tensor-pipe edge message + scatter-min
        edge_mma_kernel<<<edgeGrid, 128, SMEM_EDGE>>>(
            Abuf, src, dstp, ea, perm, w1 + (size_t)H * H,
            Bh + (size_t)l * (64 * 72), aggr, E, nt32);
        // upd1 (K=128, fused aggr decode + b2 + re-poison) -> tmp in Abuf
        node_mma<2, true, true><<<nodeBlocks, 128, smN2>>>(
            hbuf, aggr, NBh + (size_t)(l * 4 + 1) * 4608,
            ub1 + (size_t)l * H, mb2 + (size_t)l * H, aggr, Abuf, N);
        if (l < L - 1) {
            // dual: h' = tmp@uw2+ub2 -> hbuf;  A' = tmp@W'+b' -> Abuf
            node_dual<<<nodeBlocks, 128, SMEM_ND>>>(
                Abuf, ND + (size_t)(l * 2) * 4608, bdual + l * 128,
                hbuf, Abuf, N);
        } else {
            // folded tail: out = tmp @ (uw2@fcw) + (ub2.fcw + fcb)
            fc_kernel<<<(N + 255) / 256, 256>>>(Abuf, fcw2, fcw2 + 64, out, N);
        }
    }
}

// round 16
// speedup vs baseline: 1.5236x; 1.5236x over previous
#include <cuda_runtime.h>
#include <cuda_bf16.h>
#include <cuda_fp16.h>
#include <cstdint>

#define H 64
#define MAXN 100000
#define MAXE 1600000
#define MAXL 8

typedef unsigned long long u64;

// ---------------- device scratch (static: no dynamic allocation allowed) ----
__device__ float         g_h[(size_t)MAXN * H];
__device__ float         g_A[(size_t)MAXN * H];
__device__ unsigned int  g_aggr[(size_t)MAXN * H];
__device__ int           g_cnt[MAXN];
__device__ int           g_cursor[MAXN];
__device__ int           g_perm[MAXE];
__device__ __half        g_Bh[MAXL * 64 * 72];        // edge W2^T fp16 [n][72]
__device__ __half        g_NBh[MAXL * 4 * 64 * 72];   // node weights fp16 [l][g][n][72]
__device__ __half        g_ND[MAXL * 2 * 64 * 72];    // dual B: [uw2^T | (uw2@mw1')^T]
__device__ float         g_bdual[MAXL * 128];         // dual biases [ub2 | b']
__device__ float         g_fcw2[65];                  // folded fc: uw2@fcw, bias

// order-preserving float<->uint encoding for atomic min
__device__ __forceinline__ unsigned fenc(float f) {
    unsigned u = __float_as_uint(f);
    return (u & 0x80000000u) ? ~u : (u | 0x80000000u);
}
__device__ __forceinline__ float fdec(unsigned u) {
    return (u & 0x80000000u) ? __uint_as_float(u & 0x7FFFFFFFu)
                             : __uint_as_float(~u);
}

// -------- warp-mma plumbing (plain sm_80+ PTX) -----------------------------
__device__ __forceinline__ uint32_t smem_u32(const void* p) {
    uint32_t a;
    asm("{ .reg .u64 t; cvta.to.shared.u64 t, %1; cvt.u32.u64 %0, t; }"
        : "=r"(a) : "l"(p));
    return a;
}
__device__ __forceinline__ void ldsm4(uint32_t (&r)[4], uint32_t addr) {
    asm volatile("ldmatrix.sync.aligned.m8n8.x4.shared.b16 {%0,%1,%2,%3}, [%4];"
                 : "=r"(r[0]), "=r"(r[1]), "=r"(r[2]), "=r"(r[3]) : "r"(addr));
}
__device__ __forceinline__ void mma16816h(float (&d)[4], const uint32_t (&a)[4],
                                          uint32_t b0, uint32_t b1) {
    asm volatile(
        "mma.sync.aligned.m16n8k16.row.col.f32.f16.f16.f32 "
        "{%0,%1,%2,%3}, {%4,%5,%6,%7}, {%8,%9}, {%0,%1,%2,%3};"
        : "+f"(d[0]), "+f"(d[1]), "+f"(d[2]), "+f"(d[3])
        : "r"(a[0]), "r"(a[1]), "r"(a[2]), "r"(a[3]), "r"(b0), "r"(b1));
}
// pack f16(even)|f16(odd)<<16
__device__ __forceinline__ uint32_t cvt2h(float odd, float even) {
    uint32_t d;
    asm("cvt.rn.f16x2.f32 %0, %1, %2;" : "=r"(d) : "f"(odd), "f"(even));
    return d;
}

// ---------------- trivial elementwise kernels ------------------------------
__global__ void embed_kernel(const float* __restrict__ x,
                             const float* __restrict__ w,
                             const float* __restrict__ b,
                             float* __restrict__ h, int* __restrict__ cnt,
                             int n) {
    int i = blockIdx.x * blockDim.x + threadIdx.x;
    if (i < n) cnt[i] = 0;
    if (i < n * H) {
        int node = i >> 6, j = i & 63;
        h[i] = fmaf(x[node], w[j], b[j]);
    }
}

__global__ void count_kernel(const int* __restrict__ dst, int* cnt, int e) {
    int i = blockIdx.x * blockDim.x + threadIdx.x;
    if (i < e) atomicAdd(&cnt[dst[i]], 1);
}

// prefix scan of cnt + plain fp16 weight casts (O(1)/element)
__global__ void scan_prep_kernel(const int* __restrict__ cnt,
                                 int* __restrict__ cursor, int n,
                                 const float* __restrict__ mw2,
                                 const float* __restrict__ mw1,
                                 const float* __restrict__ uw1,
                                 const float* __restrict__ uw2, int L) {
    int tid = threadIdx.x;
    int total = L * H * H;
    for (int i = tid; i < total; i += 1024) {
        int l = i >> 12, rem = i & 4095;
        int nn = rem >> 6, k = rem & 63;
        float w = mw2[(size_t)l * 4096 + k * 64 + nn];
        g_Bh[(size_t)l * (64 * 72) + nn * 72 + k] = __float2half_rn(w);
    }
    int totN = L * 4 * 4096;
    for (int i = tid; i < totN; i += 1024) {
        int l = i >> 14;
        int g = (i >> 12) & 3;
        int rem = i & 4095;
        int nn = rem >> 6, k = rem & 63;
        float w;
        if (g == 0)      w = mw1[(size_t)l * 65 * 64 + k * 64 + nn];
        else if (g <= 2) w = uw1[(size_t)l * 128 * 64 + ((g - 1) * 64 + k) * 64 + nn];
        else             w = uw2[(size_t)l * 64 * 64 + k * 64 + nn];
        g_NBh[(size_t)(l * 4 + g) * 4608 + nn * 72 + k] = __float2half_rn(w);
    }
    __shared__ int s[1024];
    int chunk = (n + 1023) >> 10;
    int lo = tid * chunk;
    int hi = min(lo + chunk, n);
    int sum = 0;
    for (int i = lo; i < hi; i++) sum += cnt[i];
    s[tid] = sum;
    __syncthreads();
    for (int off = 1; off < 1024; off <<= 1) {
        int v = (tid >= off) ? s[tid - off] : 0;
        __syncthreads();
        s[tid] += v;
        __syncthreads();
    }
    int run = s[tid] - sum;
    for (int i = lo; i < hi; i++) { cursor[i] = run; run += cnt[i]; }
}

// grid-parallel weight folds: dual B, dual biases, folded fc.
// One output element per thread (the R15 version serialized this in ONE
// block -> ~500us; here it's ~1.3M FMA across the chip, ~5us).
__global__ void fold_kernel(const float* __restrict__ mw1,
                            const float* __restrict__ uw2,
                            const float* __restrict__ ub2,
                            const float* __restrict__ mb1,
                            const float* __restrict__ fcw,
                            const float* __restrict__ fcb, int L) {
    int i = blockIdx.x * blockDim.x + threadIdx.x;
    int totD = (L - 1) * 2 * 4096;
    int totB = (L - 1) * 128;
    if (i < totD) {
        int l = i >> 13;
        int g = (i >> 12) & 1;
        int rem = i & 4095;
        int nn = rem >> 6, k = rem & 63;
        float w;
        if (g == 0) {
            w = uw2[(size_t)l * 4096 + k * 64 + nn];
        } else {
            float s = 0.f;
            const float* u = uw2 + (size_t)l * 4096 + k * 64;
            const float* m = mw1 + (size_t)(l + 1) * 65 * 64;
            for (int j = 0; j < 64; j++) s += u[j] * m[j * 64 + nn];
            w = s;
        }
        g_ND[(size_t)(l * 2 + g) * 4608 + nn * 72 + k] = __float2half_rn(w);
    } else if (i < totD + totB) {
        int r = i - totD;
        int l = r >> 7, c = r & 127;
        if (c < 64) {
            g_bdual[l * 128 + c] = ub2[(size_t)l * 64 + c];
        } else {
            int nn = c - 64;
            float s = mb1[(size_t)(l + 1) * 64 + nn];
            const float* m = mw1 + (size_t)(l + 1) * 65 * 64;
            for (int j = 0; j < 64; j++)
                s += ub2[(size_t)l * 64 + j] * m[j * 64 + nn];
            g_bdual[l * 128 + c] = s;
        }
    } else if (i < totD + totB + 65) {
        int r = i - totD - totB;
        if (r < 64) {
            float s = 0.f;
            const float* u = uw2 + (size_t)(L - 1) * 4096 + r * 64;
            for (int j = 0; j < 64; j++) s += u[j] * fcw[j];
            g_fcw2[r] = s;
        } else {
            float s = fcb[0];
            for (int j = 0; j < 64; j++)
                s += ub2[(size_t)(L - 1) * 64 + j] * fcw[j];
            g_fcw2[64] = s;
        }
    }
}

// scatter (build perm) + init aggr to encoded +inf
__global__ void scatter_kernel(const int* __restrict__ dst, int* cursor,
                               int* perm, unsigned* __restrict__ aggr,
                               int e, int nH4) {
    int i = blockIdx.x * blockDim.x + threadIdx.x;
    if (i < e) {
        int p = atomicAdd(&cursor[dst[i]], 1);
        perm[p] = i;
    }
    uint4 f = make_uint4(~0u, ~0u, ~0u, ~0u);
    for (int j = i; j < nH4; j += gridDim.x * blockDim.x)
        ((uint4*)aggr)[j] = f;
}

__global__ void fc_kernel(const float* __restrict__ h,
                          const float* __restrict__ fcw,
                          const float* __restrict__ fcb,
                          float* __restrict__ out, int n) {
    int i = blockIdx.x * blockDim.x + threadIdx.x;
    if (i >= n) return;
    const float4* h4 = (const float4*)(h + (size_t)i * H);
    const float4* w4 = (const float4*)fcw;
    float s = 0.f;
#pragma unroll
    for (int q = 0; q < 16; q++) {
        float4 a = h4[q], w = w4[q];
        s += a.x * w.x + a.y * w.y + a.z * w.z + a.w * w.w;
    }
    out[i] = s + fcb[0];
}

// ---------------- node GEMM via HMMA, single-term fp16 ---------------------
#define NM_B_OFF 18432

template <int NC, bool RELU, bool DECODE>
__global__ void __launch_bounds__(128, 4)
node_mma(const float* __restrict__ X1, const unsigned* __restrict__ X2,
         const __half* __restrict__ NBh_g,
         const float* __restrict__ bias, const float* __restrict__ b2g,
         unsigned* __restrict__ aggrw, float* __restrict__ C, int Nn) {
    extern __shared__ char smc[];
    uint32_t sb = smem_u32(smc);
    int tid = threadIdx.x;
    int lane = tid & 31;
    int wid = tid >> 5;
    const int BIAS_OFF = NM_B_OFF + NC * 9216;

    {
        const uint4* sh = (const uint4*)NBh_g;
        for (int i = tid; i < NC * 576; i += 128)
            ((uint4*)(smc + NM_B_OFF))[i] = sh[i];
        if (tid < 64) ((float*)(smc + BIAS_OFF))[tid] = bias[tid];
        if (DECODE && tid >= 64 && tid < 128)
            ((float*)(smc + BIAS_OFF))[tid] = b2g[tid - 64];
    }
    __syncthreads();

    int n0 = blockIdx.x * 128;
    int m0base = n0 + wid * 32;
    char* Tw = smc + wid * 4608;
    uint32_t sbT = sb + wid * 4608;

    uint32_t aRow = (lane & 7) + 8u * ((lane >> 3) & 1);
    uint32_t aKoff = 16u * (lane >> 4);
    uint32_t bBase = 144u * (8u * ((lane >> 4) & 1) + (lane & 7)) +
                     16u * ((lane >> 3) & 1);
    int gc = lane & 15, gh = lane >> 4;

    float acc[2][8][4];
#pragma unroll
    for (int mt = 0; mt < 2; mt++)
#pragma unroll
        for (int nt = 0; nt < 8; nt++)
#pragma unroll
            for (int c = 0; c < 4; c++) acc[mt][nt][c] = 0.f;

#pragma unroll
    for (int c = 0; c < NC; c++) {
#pragma unroll 4
        for (int rp = 0; rp < 16; rp++) {
            int r = rp * 2 + gh;
            int rowu = m0base + r;
            int row = min(rowu, Nn - 1);
            float v0, v1, v2, v3;
            if (DECODE && c == 1) {
                uint4 u = ((const uint4*)(X2 + (size_t)row * H))[gc];
                float4 b2v = ((const float4*)(smc + BIAS_OFF + 256))[gc];
                v0 = (u.x >= 0xFF800000u) ? 0.f : (fdec(u.x) + b2v.x);
                v1 = (u.y >= 0xFF800000u) ? 0.f : (fdec(u.y) + b2v.y);
                v2 = (u.z >= 0xFF800000u) ? 0.f : (fdec(u.z) + b2v.z);
                v3 = (u.w >= 0xFF800000u) ? 0.f : (fdec(u.w) + b2v.w);
                if (rowu < Nn)
                    ((uint4*)(aggrw + (size_t)row * H))[gc] =
                        make_uint4(~0u, ~0u, ~0u, ~0u);
            } else {
                float4 a = ((const float4*)(X1 + (size_t)row * H))[gc];
                v0 = a.x; v1 = a.y; v2 = a.z; v3 = a.w;
            }
            *(uint2*)(Tw + r * 144 + gc * 8) =
                make_uint2(cvt2h(v1, v0), cvt2h(v3, v2));
        }
        __syncwarp();

        uint32_t Bc = sb + NM_B_OFF + c * 9216;
#pragma unroll
        for (int ks = 0; ks < 4; ks++) {
            uint32_t ah0[4], ah1[4];
            ldsm4(ah0, sbT + 144u * aRow + 32u * ks + aKoff);
            ldsm4(ah1, sbT + 144u * (16 + aRow) + 32u * ks + aKoff);
#pragma unroll
            for (int ntp = 0; ntp < 4; ntp++) {
                uint32_t bh[4];
                ldsm4(bh, Bc + bBase + 2304u * ntp + 32u * ks);
                mma16816h(acc[0][2 * ntp], ah0, bh[0], bh[1]);
                mma16816h(acc[1][2 * ntp], ah1, bh[0], bh[1]);
                mma16816h(acc[0][2 * ntp + 1], ah0, bh[2], bh[3]);
                mma16816h(acc[1][2 * ntp + 1], ah1, bh[2], bh[3]);
            }
        }
        __syncwarp();
    }

    const float* bs = (const float*)(smc + BIAS_OFF);
#pragma unroll
    for (int mt = 0; mt < 2; mt++) {
        int row = m0base + mt * 16 + (lane >> 2);
        int colb = (lane & 3) * 2;
#pragma unroll
        for (int nt = 0; nt < 8; nt++) {
            int cc = nt * 8 + colb;
            float b0 = bs[cc], b1 = bs[cc + 1];
            float2 v0 = make_float2(acc[mt][nt][0] + b0, acc[mt][nt][1] + b1);
            float2 v1 = make_float2(acc[mt][nt][2] + b0, acc[mt][nt][3] + b1);
            if (RELU) {
                v0.x = fmaxf(v0.x, 0.f); v0.y = fmaxf(v0.y, 0.f);
                v1.x = fmaxf(v1.x, 0.f); v1.y = fmaxf(v1.y, 0.f);
            }
            if (row < Nn)
                *(float2*)(C + (size_t)row * H + cc) = v0;
            if (row + 8 < Nn)
                *(float2*)(C + (size_t)(row + 8) * H + cc) = v1;
        }
    }
}

// ---------------- dual-output node GEMM ------------------------------------
// From one T (tmp): h' = tmp @ uw2 + ub2 -> hout; A' = tmp @ W' + b' -> Aout
// (W' = uw2 @ mw1_{l+1} pre-multiplied fp32->fp16). In-place safe: each warp
// reads its own 32 tmp rows into smem before the epilogue writes them.
#define ND_B_OFF 18432
#define ND_BIAS  36864
#define SMEM_ND  37376

__global__ void __launch_bounds__(128, 4)
node_dual(const float* __restrict__ X1, const __half* __restrict__ Bg,
          const float* __restrict__ bg, float* __restrict__ hout,
          float* __restrict__ Aout, int Nn) {
    extern __shared__ char smc[];
    uint32_t sb = smem_u32(smc);
    int tid = threadIdx.x, lane = tid & 31, wid = tid >> 5;

    for (int i = tid; i < 1152; i += 128)
        ((uint4*)(smc + ND_B_OFF))[i] = ((const uint4*)Bg)[i];
    if (tid < 128) ((float*)(smc + ND_BIAS))[tid] = bg[tid];
    __syncthreads();

    int m0base = blockIdx.x * 128 + wid * 32;
    char* Tw = smc + wid * 4608;
    uint32_t sbT = sb + wid * 4608;

    uint32_t aRow = (lane & 7) + 8u * ((lane >> 3) & 1);
    uint32_t aKoff = 16u * (lane >> 4);
    uint32_t bBase = 144u * (8u * ((lane >> 4) & 1) + (lane & 7)) +
                     16u * ((lane >> 3) & 1);
    int gc = lane & 15, gh = lane >> 4;

    // T-fill (coalesced, fp16)
#pragma unroll 4
    for (int rp = 0; rp < 16; rp++) {
        int r = rp * 2 + gh;
        int row = min(m0base + r, Nn - 1);
        float4 a = ((const float4*)(X1 + (size_t)row * H))[gc];
        *(uint2*)(Tw + r * 144 + gc * 8) =
            make_uint2(cvt2h(a.y, a.x), cvt2h(a.w, a.z));
    }
    __syncwarp();

    const float* bs = (const float*)(smc + ND_BIAS);
#pragma unroll
    for (int nh = 0; nh < 2; nh++) {
        float acc[2][8][4];
#pragma unroll
        for (int mt = 0; mt < 2; mt++)
#pragma unroll
            for (int nt = 0; nt < 8; nt++)
#pragma unroll
                for (int c = 0; c < 4; c++) acc[mt][nt][c] = 0.f;

        uint32_t Bc = sb + ND_B_OFF + nh * 9216;
#pragma unroll
        for (int ks = 0; ks < 4; ks++) {
            uint32_t ah0[4], ah1[4];
            ldsm4(ah0, sbT + 144u * aRow + 32u * ks + aKoff);
            ldsm4(ah1, sbT + 144u * (16 + aRow) + 32u * ks + aKoff);
#pragma unroll
            for (int ntp = 0; ntp < 4; ntp++) {
                uint32_t bh[4];
                ldsm4(bh, Bc + bBase + 2304u * ntp + 32u * ks);
                mma16816h(acc[0][2 * ntp], ah0, bh[0], bh[1]);
                mma16816h(acc[1][2 * ntp], ah1, bh[0], bh[1]);
                mma16816h(acc[0][2 * ntp + 1], ah0, bh[2], bh[3]);
                mma16816h(acc[1][2 * ntp + 1], ah1, bh[2], bh[3]);
            }
        }

        float* C = nh ? Aout : hout;
        const float* bb = bs + nh * 64;
#pragma unroll
        for (int mt = 0; mt < 2; mt++) {
            int row = m0base + mt * 16 + (lane >> 2);
            int colb = (lane & 3) * 2;
#pragma unroll
            for (int nt = 0; nt < 8; nt++) {
                int cc = nt * 8 + colb;
                float b0 = bb[cc], b1 = bb[cc + 1];
                float2 v0 = make_float2(acc[mt][nt][0] + b0,
                                        acc[mt][nt][1] + b1);
                float2 v1 = make_float2(acc[mt][nt][2] + b0,
                                        acc[mt][nt][3] + b1);
                if (row < Nn)
                    *(float2*)(C + (size_t)row * H + cc) = v0;
                if (row + 8 < Nn)
                    *(float2*)(C + (size_t)(row + 8) * H + cc) = v1;
            }
        }
    }
}

// ---------------- HMMA edge kernel (R13: coalesced + metadata prefetch) ----
#define TW_STRIDE 8192
#define BH_OFF   32768
#define WES_OFF  41984
#define DST_OFF  42240
#define SMEM_EDGE 42752

__global__ void __launch_bounds__(128, 4)
edge_mma_kernel(const float* __restrict__ Ag, const int* __restrict__ src,
                const int* __restrict__ dstp, const float* __restrict__ ea,
                const int* __restrict__ perm, const float* __restrict__ weg,
                const __half* __restrict__ Bh_g,
                unsigned* __restrict__ aggr, int E, int nt32) {
    extern __shared__ char smc[];
    uint32_t sb = smem_u32(smc);
    int tid = threadIdx.x;
    int lane = tid & 31;
    int wid = tid >> 5;

    {
        const uint4* s4 = (const uint4*)Bh_g;
        uint4* d4 = (uint4*)(smc + BH_OFF);
        for (int i = tid; i < 576; i += 128) d4[i] = s4[i];
        if (tid < 64) ((float*)(smc + WES_OFF))[tid] = weg[tid];
    }
    __syncthreads();

    const float* wes = (const float*)(smc + WES_OFF);
    char* Tw = smc + wid * TW_STRIDE;
    uint32_t sbT = sb + wid * TW_STRIDE;
    float* Ds = (float*)Tw;
    int* dstw = (int*)(smc + DST_OFF + wid * 128);

    uint32_t aRow = (lane & 7) + 8u * ((lane >> 3) & 1);
    uint32_t aKoff = 16u * (lane >> 4);
    uint32_t bBase = 144u * (8u * ((lane >> 4) & 1) + (lane & 7)) +
                     16u * ((lane >> 3) & 1);

    int gc = lane & 15;
    int ghalf = lane >> 4;
    float4 wch = ((const float4*)wes)[gc];

    int step = gridDim.x * 4;
    int t = blockIdx.x * 4 + wid;

    // preload first tile's metadata (perm -> src/ea/dst chain)
    int s = 0, dv = -1;
    float ev = 0.f;
    if (t < nt32) {
        int slot = t * 32 + lane;
        int eidx = perm[min(slot, E - 1)];
        s = src[eidx];
        ev = ea[eidx];
        dv = (slot < E) ? dstp[eidx] : -1;
    }

    for (; t < nt32; t += step) {
        dstw[lane] = dv;
        // ---- coalesced gather + relu + fp16 -> T rows (uses s, ev) ----
#pragma unroll
        for (int rp = 0; rp < 16; rp++) {
            int r = rp * 2 + ghalf;
            int srow = __shfl_sync(0xFFFFFFFFu, s, r);
            float evr = __shfl_sync(0xFFFFFFFFu, ev, r);
            float4 a = ((const float4*)(Ag + (size_t)srow * H))[gc];
            float v0 = fmaxf(fmaf(evr, wch.x, a.x), 0.f);
            float v1 = fmaxf(fmaf(evr, wch.y, a.y), 0.f);
            float v2 = fmaxf(fmaf(evr, wch.z, a.z), 0.f);
            float v3 = fmaxf(fmaf(evr, wch.w, a.w), 0.f);
            uint2 hp;
            hp.x = cvt2h(v1, v0);
            hp.y = cvt2h(v3, v2);
            *(uint2*)(Tw + r * 144 + gc * 8) = hp;
        }
        __syncwarp();

        // ---- prefetch next tile's metadata (overlaps MMA + epilogue) ----
        {
            int tn = t + step;
            if (tn < nt32) {
                int slotn = tn * 32 + lane;
                int eidxn = perm[min(slotn, E - 1)];
                s = src[eidxn];
                ev = ea[eidxn];
                dv = (slotn < E) ? dstp[eidxn] : -1;
            }
        }

        // ---- warp MMA: 2 m16-tiles (rows 0/16), 4 k-steps ----
        float acc[2][8][4];
#pragma unroll
        for (int mt = 0; mt < 2; mt++)
#pragma unroll
            for (int nt = 0; nt < 8; nt++)
#pragma unroll
                for (int c = 0; c < 4; c++) acc[mt][nt][c] = 0.f;

#pragma unroll
        for (int ks = 0; ks < 4; ks++) {
            uint32_t ah0[4], ah1[4];
            ldsm4(ah0, sbT + 144u * aRow + 32u * ks + aKoff);
            ldsm4(ah1, sbT + 144u * (16 + aRow) + 32u * ks + aKoff);
#pragma unroll
            for (int ntp = 0; ntp < 4; ntp++) {
                uint32_t b4[4];
                ldsm4(b4, sb + BH_OFF + bBase + 2304u * ntp + 32u * ks);
                mma16816h(acc[0][2 * ntp], ah0, b4[0], b4[1]);
                mma16816h(acc[1][2 * ntp], ah1, b4[0], b4[1]);
                mma16816h(acc[0][2 * ntp + 1], ah0, b4[2], b4[3]);
                mma16816h(acc[1][2 * ntp + 1], ah1, b4[2], b4[3]);
            }
        }
        __syncwarp();   // T reads done before Ds overlay writes

        // ---- stage D to swizzled SMEM: float4 slot = e*16 + (c4^(e&15)) ----
#pragma unroll
        for (int mt = 0; mt < 2; mt++) {
            int eb = mt * 16 + (lane >> 2);
            int h2i = lane & 1;
            int c4b = (lane & 3) >> 1;
#pragma unroll
            for (int nt = 0; nt < 8; nt++) {
                int c4 = nt * 2 + c4b;
                float2 v0 = make_float2(acc[mt][nt][0], acc[mt][nt][1]);
                float2 v1 = make_float2(acc[mt][nt][2], acc[mt][nt][3]);
                int e0 = eb, e1 = eb + 8;
                ((float2*)(Ds + (e0 * 16 + (c4 ^ (e0 & 15))) * 4))[h2i] = v0;
                ((float2*)(Ds + (e1 * 16 + (c4 ^ (e1 & 15))) * 4))[h2i] = v1;
            }
        }
        __syncwarp();

        // ---- epilogue: segmented min over 8 sorted edges, atomicMin ----
        {
            const float4* Ds4 = (const float4*)Ds;
            int ty = lane >> 3, tx = lane & 7;
            int cur = -2;
            float4 mA, mB;
#pragma unroll
            for (int r = 0; r < 8; r++) {
                int e = ty * 8 + r;
                int d = dstw[e];
                float4 a = Ds4[e * 16 + (tx ^ (e & 15))];
                float4 b = Ds4[e * 16 + ((8 + tx) ^ (e & 15))];
                if (r == 0 || d != cur) {
                    if (r > 0 && cur >= 0) {
                        unsigned* p0 = aggr + (size_t)cur * H + tx * 4;
                        atomicMin(p0 + 0, fenc(mA.x));
                        atomicMin(p0 + 1, fenc(mA.y));
                        atomicMin(p0 + 2, fenc(mA.z));
                        atomicMin(p0 + 3, fenc(mA.w));
                        unsigned* p1 = p0 + 32;
                        atomicMin(p1 + 0, fenc(mB.x));
                        atomicMin(p1 + 1, fenc(mB.y));
                        atomicMin(p1 + 2, fenc(mB.z));
                        atomicMin(p1 + 3, fenc(mB.w));
                    }
                    cur = d;
                    mA = a; mB = b;
                } else {
                    mA.x = fminf(mA.x, a.x); mA.y = fminf(mA.y, a.y);
                    mA.z = fminf(mA.z, a.z); mA.w = fminf(mA.w, a.w);
                    mB.x = fminf(mB.x, b.x); mB.y = fminf(mB.y, b.y);
                    mB.z = fminf(mB.z, b.z); mB.w = fminf(mB.w, b.w);
                }
            }
            if (cur >= 0) {
                unsigned* p0 = aggr + (size_t)cur * H + tx * 4;
                atomicMin(p0 + 0, fenc(mA.x));
                atomicMin(p0 + 1, fenc(mA.y));
                atomicMin(p0 + 2, fenc(mA.z));
                atomicMin(p0 + 3, fenc(mA.w));
                unsigned* p1 = p0 + 32;
                atomicMin(p1 + 0, fenc(mB.x));
                atomicMin(p1 + 1, fenc(mB.y));
                atomicMin(p1 + 2, fenc(mB.z));
                atomicMin(p1 + 3, fenc(mB.w));
            }
        }
        __syncwarp();   // Ds/dstw dead before next tile's gather writes
    }
}

// ---------------- host launch ----------------------------------------------
extern "C" void kernel_launch(void* const* d_in, const int* in_sizes, int n_in,
                              void* d_out, int out_size) {
    const float* x    = (const float*)d_in[0];
    const int*   ei   = (const int*)d_in[1];
    const float* ea   = (const float*)d_in[2];
    const float* embw = (const float*)d_in[3];
    const float* embb = (const float*)d_in[4];
    const float* mw1  = (const float*)d_in[5];
    const float* mb1  = (const float*)d_in[6];
    const float* mw2  = (const float*)d_in[7];
    const float* mb2  = (const float*)d_in[8];
    const float* uw1  = (const float*)d_in[9];
    const float* ub1  = (const float*)d_in[10];
    const float* uw2  = (const float*)d_in[11];
    const float* ub2  = (const float*)d_in[12];
    const float* fcw  = (const float*)d_in[13];
    const float* fcb  = (const float*)d_in[14];
    float* out = (float*)d_out;

    int N = in_sizes[0];
    int E = in_sizes[2];
    int L = in_sizes[6] / H;
    const int* src = ei;
    const int* dstp = ei + E;

    float* hbuf; float* Abuf; unsigned* aggr;
    int* cnt; int* cursor; int* perm;
    __half* Bh; __half* NBh; __half* ND; float* bdual; float* fcw2;
    cudaGetSymbolAddress((void**)&hbuf, g_h);
    cudaGetSymbolAddress((void**)&Abuf, g_A);
    cudaGetSymbolAddress((void**)&aggr, g_aggr);
    cudaGetSymbolAddress((void**)&cnt, g_cnt);
    cudaGetSymbolAddress((void**)&cursor, g_cursor);
    cudaGetSymbolAddress((void**)&perm, g_perm);
    cudaGetSymbolAddress((void**)&Bh, g_Bh);
    cudaGetSymbolAddress((void**)&NBh, g_NBh);
    cudaGetSymbolAddress((void**)&ND, g_ND);
    cudaGetSymbolAddress((void**)&bdual, g_bdual);
    cudaGetSymbolAddress((void**)&fcw2, g_fcw2);

    const int smN1 = NM_B_OFF + 1 * 9216 + 512;   // 28160
    const int smN2 = NM_B_OFF + 2 * 9216 + 512;   // 37376
    cudaFuncSetAttribute(edge_mma_kernel,
                         cudaFuncAttributeMaxDynamicSharedMemorySize, SMEM_EDGE);
    cudaFuncSetAttribute((node_mma<1, false, false>),
                         cudaFuncAttributeMaxDynamicSharedMemorySize, smN1);
    cudaFuncSetAttribute((node_mma<2, true, true>),
                         cudaFuncAttributeMaxDynamicSharedMemorySize, smN2);
    cudaFuncSetAttribute(node_dual,
                         cudaFuncAttributeMaxDynamicSharedMemorySize, SMEM_ND);

    int nt32 = (E + 31) / 32;
    int edgeGrid = 148 * 4;
    if (edgeGrid > (nt32 + 3) / 4) edgeGrid = (nt32 + 3) / 4;
    int nodeBlocks = (N + 127) / 128;

    // embedding (+ zero cnt)
    embed_kernel<<<(N * H + 255) / 256, 256>>>(x, embw, embb, hbuf, cnt, N);
    // counting sort by dst (+ plain fp16 casts)
    count_kernel<<<(E + 255) / 256, 256>>>(dstp, cnt, E);
    scan_prep_kernel<<<1, 1024>>>(cnt, cursor, N, mw2, mw1, uw1, uw2, L);
    // grid-parallel weight folds (dual B, dual biases, folded fc)
    {
        int totFold = (L - 1) * 2 * 4096 + (L - 1) * 128 + 65;
        fold_kernel<<<(totFold + 255) / 256, 256>>>(mw1, uw2, ub2, mb1,
                                                    fcw, fcb, L);
    }
    scatter_kernel<<<(E + 255) / 256, 256>>>(dstp, cursor, perm, aggr, E,
                                             N * H / 4);

    // A_0 = h @ mw1(0)[:64] + mb1(0)
    node_mma<1, false, false><<<nodeBlocks, 128, smN1>>>(
        hbuf, nullptr, NBh, mb1, nullptr, nullptr, Abuf, N);

    for (int l = 0; l < L; l++) {
        const float* w1 = mw1 + (size_t)l * (H + 1) * H;   // [65,64]
        // tensor-pipe edge message + scatter-min
        edge_mma_kernel<<<edgeGrid, 128, SMEM_EDGE>>>(
            Abuf, src, dstp, ea, perm, w1 + (size_t)H * H,
            Bh + (size_t)l * (64 * 72), aggr, E, nt32);
        // upd1 (K=128, fused aggr decode + b2 + re-poison) -> tmp in Abuf
        node_mma<2, true, true><<<nodeBlocks, 128, smN2>>>(
            hbuf, aggr, NBh + (size_t)(l * 4 + 1) * 4608,
            ub1 + (size_t)l * H, mb2 + (size_t)l * H, aggr, Abuf, N);
        if (l < L - 1) {
            // dual: h' = tmp@uw2+ub2 -> hbuf;  A' = tmp@W'+b' -> Abuf
            node_dual<<<nodeBlocks, 128, SMEM_ND>>>(
                Abuf, ND + (size_t)(l * 2) * 4608, bdual + l * 128,
                hbuf, Abuf, N);
        } else {
            // folded tail: out = tmp @ (uw2@fcw) + (ub2.fcw + fcb)
            fc_kernel<<<(N + 255) / 256, 256>>>(Abuf, fcw2, fcw2 + 64, out, N);
        }
    }
}

// round 17
// speedup vs baseline: 1.6255x; 1.0669x over previous
#include <cuda_runtime.h>
#include <cuda_bf16.h>
#include <cuda_fp16.h>
#include <cstdint>

#define H 64
#define MAXN 100000
#define MAXE 1600000
#define MAXL 8

typedef unsigned long long u64;

// ---------------- device scratch (static: no dynamic allocation allowed) ----
__device__ __half        g_h[(size_t)MAXN * H];       // activations fp16
__device__ __half        g_A[(size_t)MAXN * H];       // msg-A / tmp fp16
__device__ unsigned int  g_aggr[(size_t)MAXN * H];    // encoded-min fp32
__device__ int           g_cnt[MAXN];
__device__ int           g_cursor[MAXN];
__device__ int           g_perm[MAXE];
__device__ __half        g_Bh[MAXL * 64 * 72];        // edge W2^T fp16 [n][72]
__device__ __half        g_NBh[MAXL * 4 * 64 * 72];   // node weights fp16
__device__ __half        g_ND[MAXL * 2 * 64 * 72];    // dual B: [uw2^T | (uw2@mw1')^T]
__device__ float         g_bdual[MAXL * 128];         // dual biases [ub2 | b']
__device__ float         g_fcw2[65];                  // folded fc: uw2@fcw, bias

// order-preserving float<->uint encoding for atomic min
__device__ __forceinline__ unsigned fenc(float f) {
    unsigned u = __float_as_uint(f);
    return (u & 0x80000000u) ? ~u : (u | 0x80000000u);
}
__device__ __forceinline__ float fdec(unsigned u) {
    return (u & 0x80000000u) ? __uint_as_float(u & 0x7FFFFFFFu)
                             : __uint_as_float(~u);
}

// -------- warp-mma plumbing (plain sm_80+ PTX) -----------------------------
__device__ __forceinline__ uint32_t smem_u32(const void* p) {
    uint32_t a;
    asm("{ .reg .u64 t; cvta.to.shared.u64 t, %1; cvt.u32.u64 %0, t; }"
        : "=r"(a) : "l"(p));
    return a;
}
__device__ __forceinline__ void ldsm4(uint32_t (&r)[4], uint32_t addr) {
    asm volatile("ldmatrix.sync.aligned.m8n8.x4.shared.b16 {%0,%1,%2,%3}, [%4];"
                 : "=r"(r[0]), "=r"(r[1]), "=r"(r[2]), "=r"(r[3]) : "r"(addr));
}
__device__ __forceinline__ void mma16816h(float (&d)[4], const uint32_t (&a)[4],
                                          uint32_t b0, uint32_t b1) {
    asm volatile(
        "mma.sync.aligned.m16n8k16.row.col.f32.f16.f16.f32 "
        "{%0,%1,%2,%3}, {%4,%5,%6,%7}, {%8,%9}, {%0,%1,%2,%3};"
        : "+f"(d[0]), "+f"(d[1]), "+f"(d[2]), "+f"(d[3])
        : "r"(a[0]), "r"(a[1]), "r"(a[2]), "r"(a[3]), "r"(b0), "r"(b1));
}
// pack f16(even)|f16(odd)<<16
__device__ __forceinline__ uint32_t cvt2h(float odd, float even) {
    uint32_t d;
    asm("cvt.rn.f16x2.f32 %0, %1, %2;" : "=r"(d) : "f"(odd), "f"(even));
    return d;
}
__device__ __forceinline__ float2 h22f2(uint32_t h) {
    __half2 hh = *(__half2*)&h;
    return __half22float2(hh);
}

// ---------------- trivial elementwise kernels ------------------------------
__global__ void embed_kernel(const float* __restrict__ x,
                             const float* __restrict__ w,
                             const float* __restrict__ b,
                             __half* __restrict__ h, int* __restrict__ cnt,
                             int n) {
    int i = blockIdx.x * blockDim.x + threadIdx.x;
    if (i < n) cnt[i] = 0;
    if (i < n * H) {
        int node = i >> 6, j = i & 63;
        h[i] = __float2half_rn(fmaf(x[node], w[j], b[j]));
    }
}

__global__ void count_kernel(const int* __restrict__ dst, int* cnt, int e) {
    int i = blockIdx.x * blockDim.x + threadIdx.x;
    if (i < e) atomicAdd(&cnt[dst[i]], 1);
}

// prefix scan of cnt + plain fp16 weight casts (O(1)/element)
__global__ void scan_prep_kernel(const int* __restrict__ cnt,
                                 int* __restrict__ cursor, int n,
                                 const float* __restrict__ mw2,
                                 const float* __restrict__ mw1,
                                 const float* __restrict__ uw1,
                                 const float* __restrict__ uw2, int L) {
    int tid = threadIdx.x;
    int total = L * H * H;
    for (int i = tid; i < total; i += 1024) {
        int l = i >> 12, rem = i & 4095;
        int nn = rem >> 6, k = rem & 63;
        float w = mw2[(size_t)l * 4096 + k * 64 + nn];
        g_Bh[(size_t)l * (64 * 72) + nn * 72 + k] = __float2half_rn(w);
    }
    int totN = L * 4 * 4096;
    for (int i = tid; i < totN; i += 1024) {
        int l = i >> 14;
        int g = (i >> 12) & 3;
        int rem = i & 4095;
        int nn = rem >> 6, k = rem & 63;
        float w;
        if (g == 0)      w = mw1[(size_t)l * 65 * 64 + k * 64 + nn];
        else if (g <= 2) w = uw1[(size_t)l * 128 * 64 + ((g - 1) * 64 + k) * 64 + nn];
        else             w = uw2[(size_t)l * 64 * 64 + k * 64 + nn];
        g_NBh[(size_t)(l * 4 + g) * 4608 + nn * 72 + k] = __float2half_rn(w);
    }
    __shared__ int s[1024];
    int chunk = (n + 1023) >> 10;
    int lo = tid * chunk;
    int hi = min(lo + chunk, n);
    int sum = 0;
    for (int i = lo; i < hi; i++) sum += cnt[i];
    s[tid] = sum;
    __syncthreads();
    for (int off = 1; off < 1024; off <<= 1) {
        int v = (tid >= off) ? s[tid - off] : 0;
        __syncthreads();
        s[tid] += v;
        __syncthreads();
    }
    int run = s[tid] - sum;
    for (int i = lo; i < hi; i++) { cursor[i] = run; run += cnt[i]; }
}

// grid-parallel weight folds: dual B, dual biases, folded fc.
__global__ void fold_kernel(const float* __restrict__ mw1,
                            const float* __restrict__ uw2,
                            const float* __restrict__ ub2,
                            const float* __restrict__ mb1,
                            const float* __restrict__ fcw,
                            const float* __restrict__ fcb, int L) {
    int i = blockIdx.x * blockDim.x + threadIdx.x;
    int totD = (L - 1) * 2 * 4096;
    int totB = (L - 1) * 128;
    if (i < totD) {
        int l = i >> 13;
        int g = (i >> 12) & 1;
        int rem = i & 4095;
        int nn = rem >> 6, k = rem & 63;
        float w;
        if (g == 0) {
            w = uw2[(size_t)l * 4096 + k * 64 + nn];
        } else {
            float s = 0.f;
            const float* u = uw2 + (size_t)l * 4096 + k * 64;
            const float* m = mw1 + (size_t)(l + 1) * 65 * 64;
            for (int j = 0; j < 64; j++) s += u[j] * m[j * 64 + nn];
            w = s;
        }
        g_ND[(size_t)(l * 2 + g) * 4608 + nn * 72 + k] = __float2half_rn(w);
    } else if (i < totD + totB) {
        int r = i - totD;
        int l = r >> 7, c = r & 127;
        if (c < 64) {
            g_bdual[l * 128 + c] = ub2[(size_t)l * 64 + c];
        } else {
            int nn = c - 64;
            float s = mb1[(size_t)(l + 1) * 64 + nn];
            const float* m = mw1 + (size_t)(l + 1) * 65 * 64;
            for (int j = 0; j < 64; j++)
                s += ub2[(size_t)l * 64 + j] * m[j * 64 + nn];
            g_bdual[l * 128 + c] = s;
        }
    } else if (i < totD + totB + 65) {
        int r = i - totD - totB;
        if (r < 64) {
            float s = 0.f;
            const float* u = uw2 + (size_t)(L - 1) * 4096 + r * 64;
            for (int j = 0; j < 64; j++) s += u[j] * fcw[j];
            g_fcw2[r] = s;
        } else {
            float s = fcb[0];
            for (int j = 0; j < 64; j++)
                s += ub2[(size_t)(L - 1) * 64 + j] * fcw[j];
            g_fcw2[64] = s;
        }
    }
}

// scatter (build perm) + init aggr to encoded +inf
__global__ void scatter_kernel(const int* __restrict__ dst, int* cursor,
                               int* perm, unsigned* __restrict__ aggr,
                               int e, int nH4) {
    int i = blockIdx.x * blockDim.x + threadIdx.x;
    if (i < e) {
        int p = atomicAdd(&cursor[dst[i]], 1);
        perm[p] = i;
    }
    uint4 f = make_uint4(~0u, ~0u, ~0u, ~0u);
    for (int j = i; j < nH4; j += gridDim.x * blockDim.x)
        ((uint4*)aggr)[j] = f;
}

__global__ void fc_kernel(const __half* __restrict__ h,
                          const float* __restrict__ fcw,
                          const float* __restrict__ fcb,
                          float* __restrict__ out, int n) {
    int i = blockIdx.x * blockDim.x + threadIdx.x;
    if (i >= n) return;
    const uint2* h2 = (const uint2*)(h + (size_t)i * H);
    const float4* w4 = (const float4*)fcw;
    float s = 0.f;
#pragma unroll
    for (int q = 0; q < 16; q++) {
        uint2 u = h2[q];
        float2 a0 = h22f2(u.x), a1 = h22f2(u.y);
        float4 w = w4[q];
        s += a0.x * w.x + a0.y * w.y + a1.x * w.z + a1.y * w.w;
    }
    out[i] = s + fcb[0];
}

// ---------------- node GEMM via HMMA, single-term fp16 ---------------------
// X1 fp16 (T-fill = pure uint2 copy). DECODE chunk-1 input = encoded aggr.
// Output C fp16.
#define NM_B_OFF 18432

template <int NC, bool RELU, bool DECODE>
__global__ void __launch_bounds__(128, 4)
node_mma(const __half* __restrict__ X1, const unsigned* __restrict__ X2,
         const __half* __restrict__ NBh_g,
         const float* __restrict__ bias, const float* __restrict__ b2g,
         unsigned* __restrict__ aggrw, __half* __restrict__ C, int Nn) {
    extern __shared__ char smc[];
    uint32_t sb = smem_u32(smc);
    int tid = threadIdx.x;
    int lane = tid & 31;
    int wid = tid >> 5;
    const int BIAS_OFF = NM_B_OFF + NC * 9216;

    {
        const uint4* sh = (const uint4*)NBh_g;
        for (int i = tid; i < NC * 576; i += 128)
            ((uint4*)(smc + NM_B_OFF))[i] = sh[i];
        if (tid < 64) ((float*)(smc + BIAS_OFF))[tid] = bias[tid];
        if (DECODE && tid >= 64 && tid < 128)
            ((float*)(smc + BIAS_OFF))[tid] = b2g[tid - 64];
    }
    __syncthreads();

    int n0 = blockIdx.x * 128;
    int m0base = n0 + wid * 32;
    char* Tw = smc + wid * 4608;
    uint32_t sbT = sb + wid * 4608;

    uint32_t aRow = (lane & 7) + 8u * ((lane >> 3) & 1);
    uint32_t aKoff = 16u * (lane >> 4);
    uint32_t bBase = 144u * (8u * ((lane >> 4) & 1) + (lane & 7)) +
                     16u * ((lane >> 3) & 1);
    int gc = lane & 15, gh = lane >> 4;

    float acc[2][8][4];
#pragma unroll
    for (int mt = 0; mt < 2; mt++)
#pragma unroll
        for (int nt = 0; nt < 8; nt++)
#pragma unroll
            for (int c = 0; c < 4; c++) acc[mt][nt][c] = 0.f;

#pragma unroll
    for (int c = 0; c < NC; c++) {
#pragma unroll 4
        for (int rp = 0; rp < 16; rp++) {
            int r = rp * 2 + gh;
            int rowu = m0base + r;
            int row = min(rowu, Nn - 1);
            if (DECODE && c == 1) {
                uint4 u = ((const uint4*)(X2 + (size_t)row * H))[gc];
                float4 b2v = ((const float4*)(smc + BIAS_OFF + 256))[gc];
                float v0 = (u.x >= 0xFF800000u) ? 0.f : (fdec(u.x) + b2v.x);
                float v1 = (u.y >= 0xFF800000u) ? 0.f : (fdec(u.y) + b2v.y);
                float v2 = (u.z >= 0xFF800000u) ? 0.f : (fdec(u.z) + b2v.z);
                float v3 = (u.w >= 0xFF800000u) ? 0.f : (fdec(u.w) + b2v.w);
                if (rowu < Nn)
                    ((uint4*)(aggrw + (size_t)row * H))[gc] =
                        make_uint4(~0u, ~0u, ~0u, ~0u);
                *(uint2*)(Tw + r * 144 + gc * 8) =
                    make_uint2(cvt2h(v1, v0), cvt2h(v3, v2));
            } else {
                uint2 a = ((const uint2*)(X1 + (size_t)row * H))[gc];
                *(uint2*)(Tw + r * 144 + gc * 8) = a;
            }
        }
        __syncwarp();

        uint32_t Bc = sb + NM_B_OFF + c * 9216;
#pragma unroll
        for (int ks = 0; ks < 4; ks++) {
            uint32_t ah0[4], ah1[4];
            ldsm4(ah0, sbT + 144u * aRow + 32u * ks + aKoff);
            ldsm4(ah1, sbT + 144u * (16 + aRow) + 32u * ks + aKoff);
#pragma unroll
            for (int ntp = 0; ntp < 4; ntp++) {
                uint32_t bh[4];
                ldsm4(bh, Bc + bBase + 2304u * ntp + 32u * ks);
                mma16816h(acc[0][2 * ntp], ah0, bh[0], bh[1]);
                mma16816h(acc[1][2 * ntp], ah1, bh[0], bh[1]);
                mma16816h(acc[0][2 * ntp + 1], ah0, bh[2], bh[3]);
                mma16816h(acc[1][2 * ntp + 1], ah1, bh[2], bh[3]);
            }
        }
        __syncwarp();
    }

    const float* bs = (const float*)(smc + BIAS_OFF);
#pragma unroll
    for (int mt = 0; mt < 2; mt++) {
        int row = m0base + mt * 16 + (lane >> 2);
        int colb = (lane & 3) * 2;
#pragma unroll
        for (int nt = 0; nt < 8; nt++) {
            int cc = nt * 8 + colb;
            float b0 = bs[cc], b1 = bs[cc + 1];
            float v00 = acc[mt][nt][0] + b0, v01 = acc[mt][nt][1] + b1;
            float v10 = acc[mt][nt][2] + b0, v11 = acc[mt][nt][3] + b1;
            if (RELU) {
                v00 = fmaxf(v00, 0.f); v01 = fmaxf(v01, 0.f);
                v10 = fmaxf(v10, 0.f); v11 = fmaxf(v11, 0.f);
            }
            if (row < Nn)
                *(uint32_t*)(C + (size_t)row * H + cc) = cvt2h(v01, v00);
            if (row + 8 < Nn)
                *(uint32_t*)(C + (size_t)(row + 8) * H + cc) = cvt2h(v11, v10);
        }
    }
}

// ---------------- dual-output node GEMM ------------------------------------
// From one T (tmp fp16): h' -> hout (fp16); A' -> Aout (fp16).
#define ND_B_OFF 18432
#define ND_BIAS  36864
#define SMEM_ND  37376

__global__ void __launch_bounds__(128, 4)
node_dual(const __half* __restrict__ X1, const __half* __restrict__ Bg,
          const float* __restrict__ bg, __half* __restrict__ hout,
          __half* __restrict__ Aout, int Nn) {
    extern __shared__ char smc[];
    uint32_t sb = smem_u32(smc);
    int tid = threadIdx.x, lane = tid & 31, wid = tid >> 5;

    for (int i = tid; i < 1152; i += 128)
        ((uint4*)(smc + ND_B_OFF))[i] = ((const uint4*)Bg)[i];
    if (tid < 128) ((float*)(smc + ND_BIAS))[tid] = bg[tid];
    __syncthreads();

    int m0base = blockIdx.x * 128 + wid * 32;
    char* Tw = smc + wid * 4608;
    uint32_t sbT = sb + wid * 4608;

    uint32_t aRow = (lane & 7) + 8u * ((lane >> 3) & 1);
    uint32_t aKoff = 16u * (lane >> 4);
    uint32_t bBase = 144u * (8u * ((lane >> 4) & 1) + (lane & 7)) +
                     16u * ((lane >> 3) & 1);
    int gc = lane & 15, gh = lane >> 4;

    // T-fill (pure fp16 copy)
#pragma unroll 4
    for (int rp = 0; rp < 16; rp++) {
        int r = rp * 2 + gh;
        int row = min(m0base + r, Nn - 1);
        uint2 a = ((const uint2*)(X1 + (size_t)row * H))[gc];
        *(uint2*)(Tw + r * 144 + gc * 8) = a;
    }
    __syncwarp();

    const float* bs = (const float*)(smc + ND_BIAS);
#pragma unroll
    for (int nh = 0; nh < 2; nh++) {
        float acc[2][8][4];
#pragma unroll
        for (int mt = 0; mt < 2; mt++)
#pragma unroll
            for (int nt = 0; nt < 8; nt++)
#pragma unroll
                for (int c = 0; c < 4; c++) acc[mt][nt][c] = 0.f;

        uint32_t Bc = sb + ND_B_OFF + nh * 9216;
#pragma unroll
        for (int ks = 0; ks < 4; ks++) {
            uint32_t ah0[4], ah1[4];
            ldsm4(ah0, sbT + 144u * aRow + 32u * ks + aKoff);
            ldsm4(ah1, sbT + 144u * (16 + aRow) + 32u * ks + aKoff);
#pragma unroll
            for (int ntp = 0; ntp < 4; ntp++) {
                uint32_t bh[4];
                ldsm4(bh, Bc + bBase + 2304u * ntp + 32u * ks);
                mma16816h(acc[0][2 * ntp], ah0, bh[0], bh[1]);
                mma16816h(acc[1][2 * ntp], ah1, bh[0], bh[1]);
                mma16816h(acc[0][2 * ntp + 1], ah0, bh[2], bh[3]);
                mma16816h(acc[1][2 * ntp + 1], ah1, bh[2], bh[3]);
            }
        }

        __half* C = nh ? Aout : hout;
        const float* bb = bs + nh * 64;
#pragma unroll
        for (int mt = 0; mt < 2; mt++) {
            int row = m0base + mt * 16 + (lane >> 2);
            int colb = (lane & 3) * 2;
#pragma unroll
            for (int nt = 0; nt < 8; nt++) {
                int cc = nt * 8 + colb;
                float b0 = bb[cc], b1 = bb[cc + 1];
                if (row < Nn)
                    *(uint32_t*)(C + (size_t)row * H + cc) =
                        cvt2h(acc[mt][nt][1] + b1, acc[mt][nt][0] + b0);
                if (row + 8 < Nn)
                    *(uint32_t*)(C + (size_t)(row + 8) * H + cc) =
                        cvt2h(acc[mt][nt][3] + b1, acc[mt][nt][2] + b0);
            }
        }
    }
}

// ---------------- HMMA edge kernel (coalesced fp16 gather + prefetch) ------
// A rows now fp16 (128B = 1 cache line): gather wavefronts/tile 64 -> 32.
#define TW_STRIDE 8192
#define BH_OFF   32768
#define WES_OFF  41984
#define DST_OFF  42240
#define SMEM_EDGE 42752

__global__ void __launch_bounds__(128, 4)
edge_mma_kernel(const __half* __restrict__ Ag, const int* __restrict__ src,
                const int* __restrict__ dstp, const float* __restrict__ ea,
                const int* __restrict__ perm, const float* __restrict__ weg,
                const __half* __restrict__ Bh_g,
                unsigned* __restrict__ aggr, int E, int nt32) {
    extern __shared__ char smc[];
    uint32_t sb = smem_u32(smc);
    int tid = threadIdx.x;
    int lane = tid & 31;
    int wid = tid >> 5;

    {
        const uint4* s4 = (const uint4*)Bh_g;
        uint4* d4 = (uint4*)(smc + BH_OFF);
        for (int i = tid; i < 576; i += 128) d4[i] = s4[i];
        if (tid < 64) ((float*)(smc + WES_OFF))[tid] = weg[tid];
    }
    __syncthreads();

    const float* wes = (const float*)(smc + WES_OFF);
    char* Tw = smc + wid * TW_STRIDE;
    uint32_t sbT = sb + wid * TW_STRIDE;
    float* Ds = (float*)Tw;
    int* dstw = (int*)(smc + DST_OFF + wid * 128);

    uint32_t aRow = (lane & 7) + 8u * ((lane >> 3) & 1);
    uint32_t aKoff = 16u * (lane >> 4);
    uint32_t bBase = 144u * (8u * ((lane >> 4) & 1) + (lane & 7)) +
                     16u * ((lane >> 3) & 1);

    int gc = lane & 15;
    int ghalf = lane >> 4;
    float4 wch = ((const float4*)wes)[gc];

    int step = gridDim.x * 4;
    int t = blockIdx.x * 4 + wid;

    // preload first tile's metadata (perm -> src/ea/dst chain)
    int s = 0, dv = -1;
    float ev = 0.f;
    if (t < nt32) {
        int slot = t * 32 + lane;
        int eidx = perm[min(slot, E - 1)];
        s = src[eidx];
        ev = ea[eidx];
        dv = (slot < E) ? dstp[eidx] : -1;
    }

    for (; t < nt32; t += step) {
        dstw[lane] = dv;
        // ---- coalesced fp16 gather + relu -> T rows ----
#pragma unroll
        for (int rp = 0; rp < 16; rp++) {
            int r = rp * 2 + ghalf;
            int srow = __shfl_sync(0xFFFFFFFFu, s, r);
            float evr = __shfl_sync(0xFFFFFFFFu, ev, r);
            uint2 ap = ((const uint2*)(Ag + (size_t)srow * H))[gc];
            float2 f0 = h22f2(ap.x), f1 = h22f2(ap.y);
            float v0 = fmaxf(fmaf(evr, wch.x, f0.x), 0.f);
            float v1 = fmaxf(fmaf(evr, wch.y, f0.y), 0.f);
            float v2 = fmaxf(fmaf(evr, wch.z, f1.x), 0.f);
            float v3 = fmaxf(fmaf(evr, wch.w, f1.y), 0.f);
            uint2 hp;
            hp.x = cvt2h(v1, v0);
            hp.y = cvt2h(v3, v2);
            *(uint2*)(Tw + r * 144 + gc * 8) = hp;
        }
        __syncwarp();

        // ---- prefetch next tile's metadata (overlaps MMA + epilogue) ----
        {
            int tn = t + step;
            if (tn < nt32) {
                int slotn = tn * 32 + lane;
                int eidxn = perm[min(slotn, E - 1)];
                s = src[eidxn];
                ev = ea[eidxn];
                dv = (slotn < E) ? dstp[eidxn] : -1;
            }
        }

        // ---- warp MMA: 2 m16-tiles (rows 0/16), 4 k-steps ----
        float acc[2][8][4];
#pragma unroll
        for (int mt = 0; mt < 2; mt++)
#pragma unroll
            for (int nt = 0; nt < 8; nt++)
#pragma unroll
                for (int c = 0; c < 4; c++) acc[mt][nt][c] = 0.f;

#pragma unroll
        for (int ks = 0; ks < 4; ks++) {
            uint32_t ah0[4], ah1[4];
            ldsm4(ah0, sbT + 144u * aRow + 32u * ks + aKoff);
            ldsm4(ah1, sbT + 144u * (16 + aRow) + 32u * ks + aKoff);
#pragma unroll
            for (int ntp = 0; ntp < 4; ntp++) {
                uint32_t b4[4];
                ldsm4(b4, sb + BH_OFF + bBase + 2304u * ntp + 32u * ks);
                mma16816h(acc[0][2 * ntp], ah0, b4[0], b4[1]);
                mma16816h(acc[1][2 * ntp], ah1, b4[0], b4[1]);
                mma16816h(acc[0][2 * ntp + 1], ah0, b4[2], b4[3]);
                mma16816h(acc[1][2 * ntp + 1], ah1, b4[2], b4[3]);
            }
        }
        __syncwarp();   // T reads done before Ds overlay writes

        // ---- stage D to swizzled SMEM: float4 slot = e*16 + (c4^(e&15)) ----
#pragma unroll
        for (int mt = 0; mt < 2; mt++) {
            int eb = mt * 16 + (lane >> 2);
            int h2i = lane & 1;
            int c4b = (lane & 3) >> 1;
#pragma unroll
            for (int nt = 0; nt < 8; nt++) {
                int c4 = nt * 2 + c4b;
                float2 v0 = make_float2(acc[mt][nt][0], acc[mt][nt][1]);
                float2 v1 = make_float2(acc[mt][nt][2], acc[mt][nt][3]);
                int e0 = eb, e1 = eb + 8;
                ((float2*)(Ds + (e0 * 16 + (c4 ^ (e0 & 15))) * 4))[h2i] = v0;
                ((float2*)(Ds + (e1 * 16 + (c4 ^ (e1 & 15))) * 4))[h2i] = v1;
            }
        }
        __syncwarp();

        // ---- epilogue: segmented min over 8 sorted edges, atomicMin ----
        {
            const float4* Ds4 = (const float4*)Ds;
            int ty = lane >> 3, tx = lane & 7;
            int cur = -2;
            float4 mA, mB;
#pragma unroll
            for (int r = 0; r < 8; r++) {
                int e = ty * 8 + r;
                int d = dstw[e];
                float4 a = Ds4[e * 16 + (tx ^ (e & 15))];
                float4 b = Ds4[e * 16 + ((8 + tx) ^ (e & 15))];
                if (r == 0 || d != cur) {
                    if (r > 0 && cur >= 0) {
                        unsigned* p0 = aggr + (size_t)cur * H + tx * 4;
                        atomicMin(p0 + 0, fenc(mA.x));
                        atomicMin(p0 + 1, fenc(mA.y));
                        atomicMin(p0 + 2, fenc(mA.z));
                        atomicMin(p0 + 3, fenc(mA.w));
                        unsigned* p1 = p0 + 32;
                        atomicMin(p1 + 0, fenc(mB.x));
                        atomicMin(p1 + 1, fenc(mB.y));
                        atomicMin(p1 + 2, fenc(mB.z));
                        atomicMin(p1 + 3, fenc(mB.w));
                    }
                    cur = d;
                    mA = a; mB = b;
                } else {
                    mA.x = fminf(mA.x, a.x); mA.y = fminf(mA.y, a.y);
                    mA.z = fminf(mA.z, a.z); mA.w = fminf(mA.w, a.w);
                    mB.x = fminf(mB.x, b.x); mB.y = fminf(mB.y, b.y);
                    mB.z = fminf(mB.z, b.z); mB.w = fminf(mB.w, b.w);
                }
            }
            if (cur >= 0) {
                unsigned* p0 = aggr + (size_t)cur * H + tx * 4;
                atomicMin(p0 + 0, fenc(mA.x));
                atomicMin(p0 + 1, fenc(mA.y));
                atomicMin(p0 + 2, fenc(mA.z));
                atomicMin(p0 + 3, fenc(mA.w));
                unsigned* p1 = p0 + 32;
                atomicMin(p1 + 0, fenc(mB.x));
                atomicMin(p1 + 1, fenc(mB.y));
                atomicMin(p1 + 2, fenc(mB.z));
                atomicMin(p1 + 3, fenc(mB.w));
            }
        }
        __syncwarp();   // Ds/dstw dead before next tile's gather writes
    }
}

// ---------------- host launch ----------------------------------------------
extern "C" void kernel_launch(void* const* d_in, const int* in_sizes, int n_in,
                              void* d_out, int out_size) {
    const float* x    = (const float*)d_in[0];
    const int*   ei   = (const int*)d_in[1];
    const float* ea   = (const float*)d_in[2];
    const float* embw = (const float*)d_in[3];
    const float* embb = (const float*)d_in[4];
    const float* mw1  = (const float*)d_in[5];
    const float* mb1  = (const float*)d_in[6];
    const float* mw2  = (const float*)d_in[7];
    const float* mb2  = (const float*)d_in[8];
    const float* uw1  = (const float*)d_in[9];
    const float* ub1  = (const float*)d_in[10];
    const float* uw2  = (const float*)d_in[11];
    const float* ub2  = (const float*)d_in[12];
    const float* fcw  = (const float*)d_in[13];
    const float* fcb  = (const float*)d_in[14];
    float* out = (float*)d_out;

    int N = in_sizes[0];
    int E = in_sizes[2];
    int L = in_sizes[6] / H;
    const int* src = ei;
    const int* dstp = ei + E;

    __half* hbuf; __half* Abuf; unsigned* aggr;
    int* cnt; int* cursor; int* perm;
    __half* Bh; __half* NBh; __half* ND; float* bdual; float* fcw2;
    cudaGetSymbolAddress((void**)&hbuf, g_h);
    cudaGetSymbolAddress((void**)&Abuf, g_A);
    cudaGetSymbolAddress((void**)&aggr, g_aggr);
    cudaGetSymbolAddress((void**)&cnt, g_cnt);
    cudaGetSymbolAddress((void**)&cursor, g_cursor);
    cudaGetSymbolAddress((void**)&perm, g_perm);
    cudaGetSymbolAddress((void**)&Bh, g_Bh);
    cudaGetSymbolAddress((void**)&NBh, g_NBh);
    cudaGetSymbolAddress((void**)&ND, g_ND);
    cudaGetSymbolAddress((void**)&bdual, g_bdual);
    cudaGetSymbolAddress((void**)&fcw2, g_fcw2);

    const int smN1 = NM_B_OFF + 1 * 9216 + 512;   // 28160
    const int smN2 = NM_B_OFF + 2 * 9216 + 512;   // 37376
    cudaFuncSetAttribute(edge_mma_kernel,
                         cudaFuncAttributeMaxDynamicSharedMemorySize, SMEM_EDGE);
    cudaFuncSetAttribute((node_mma<1, false, false>),
                         cudaFuncAttributeMaxDynamicSharedMemorySize, smN1);
    cudaFuncSetAttribute((node_mma<2, true, true>),
                         cudaFuncAttributeMaxDynamicSharedMemorySize, smN2);
    cudaFuncSetAttribute(node_dual,
                         cudaFuncAttributeMaxDynamicSharedMemorySize, SMEM_ND);

    int nt32 = (E + 31) / 32;
    int edgeGrid = 148 * 4;
    if (edgeGrid > (nt32 + 3) / 4) edgeGrid = (nt32 + 3) / 4;
    int nodeBlocks = (N + 127) / 128;

    // embedding (+ zero cnt)
    embed_kernel<<<(N * H + 255) / 256, 256>>>(x, embw, embb, hbuf, cnt, N);
    // counting sort by dst (+ plain fp16 casts)
    count_kernel<<<(E + 255) / 256, 256>>>(dstp, cnt, E);
    scan_prep_kernel<<<1, 1024>>>(cnt, cursor, N, mw2, mw1, uw1, uw2, L);
    // grid-parallel weight folds (dual B, dual biases, folded fc)
    {
        int totFold = (L - 1) * 2 * 4096 + (L - 1) * 128 + 65;
        fold_kernel<<<(totFold + 255) / 256, 256>>>(mw1, uw2, ub2, mb1,
                                                    fcw, fcb, L);
    }
    scatter_kernel<<<(E + 255) / 256, 256>>>(dstp, cursor, perm, aggr, E,
                                             N * H / 4);

    // A_0 = h @ mw1(0)[:64] + mb1(0)
    node_mma<1, false, false><<<nodeBlocks, 128, smN1>>>(
        hbuf, nullptr, NBh, mb1, nullptr, nullptr, Abuf, N);

    for (int l = 0; l < L; l++) {
        const float* w1 = mw1 + (size_t)l * (H + 1) * H;   // [65,64]
        // tensor-pipe edge message + scatter-min (fp16 gather, 1 line/row)
        edge_mma_kernel<<<edgeGrid, 128, SMEM_EDGE>>>(
            Abuf, src, dstp, ea, perm, w1 + (size_t)H * H,
            Bh + (size_t)l * (64 * 72), aggr, E, nt32);
        // upd1 (K=128, fused aggr decode + b2 + re-poison) -> tmp in Abuf
        node_mma<2, true, true><<<nodeBlocks, 128, smN2>>>(
            hbuf, aggr, NBh + (size_t)(l * 4 + 1) * 4608,
            ub1 + (size_t)l * H, mb2 + (size_t)l * H, aggr, Abuf, N);
        if (l < L - 1) {
            // dual: h' = tmp@uw2+ub2 -> hbuf;  A' = tmp@W'+b' -> Abuf
            node_dual<<<nodeBlocks, 128, SMEM_ND>>>(
                Abuf, ND + (size_t)(l * 2) * 4608, bdual + l * 128,
                hbuf, Abuf, N);
        } else {
            // folded tail: out = tmp @ (uw2@fcw) + (ub2.fcw + fcb)
            fc_kernel<<<(N + 255) / 256, 256>>>(Abuf, fcw2, fcw2 + 64, out, N);
        }
    }
}